// round 7
// baseline (speedup 1.0000x reference)
#include <cuda_runtime.h>
#include <cuda_fp16.h>

#define NROWS   16384
#define INC     512
#define NG      64
#define NF      24
#define NO      16
#define ACCC    3584
#define RT      32
#define NTHR    1024
#define SMEM_BYTES (ACCC * RT * 2)   // 229376 bytes (fp16)

typedef unsigned long long u64;

static __device__ __forceinline__ u64 pk2(float a, float b) {
    u64 r;
    asm("mov.b64 %0, {%1, %2};" : "=l"(r) : "f"(a), "f"(b));
    return r;
}
static __device__ __forceinline__ void up2(u64 v, float &a, float &b) {
    asm("mov.b64 {%0, %1}, %2;" : "=f"(a), "=f"(b) : "l"(v));
}
static __device__ __forceinline__ u64 fma2(u64 a, u64 b, u64 c) {
    u64 d;
    asm("fma.rn.f32x2 %0, %1, %2, %3;" : "=l"(d) : "l"(a), "l"(b), "l"(c));
    return d;
}
static __device__ __forceinline__ float tanhhw(float x) {
    float y;
    asm("tanh.approx.f32 %0, %1;" : "=f"(y) : "f"(x));
    return y;
}

// fp16 tile [col][32 rows]; row-pair p = r/2 stored as one half2 (4B).
// Physical 4B slot = p ^ HASH15(c). HASH15 mixes low col bits (spreads the
// staging stores, where c varies across lanes) and bit-4+ (spreads the
// writeback, where cols across a warp differ by 16).
#define HASH15(c)  ((((c) ^ ((c) >> 4)) & 15))

static __device__ __forceinline__ __half2* pp(__half* sh, int c, int p) {
    return reinterpret_cast<__half2*>(sh + c * RT) + (p ^ HASH15(c));
}
static __device__ __forceinline__ const __half2* ppc(const __half* sh, int c, int p) {
    return reinterpret_cast<const __half2*>(sh + c * RT) + (p ^ HASH15(c));
}

// Thread = (g, p): group g, row-pair p (rows 2p, 2p+1), all 16 outputs.
// acc[r][op] = f32x2 over outputs (2op, 2op+1) for local row r.
static __device__ __forceinline__ void glayer(__half* sh, int g, int p,
                                              const float* __restrict__ W,
                                              const float* __restrict__ bia,
                                              const int* __restrict__ idx,
                                              int colbase)
{
    u64 acc[2][8];
    {
        const float2* b2 = reinterpret_cast<const float2*>(bia + g * NO);
        #pragma unroll
        for (int op = 0; op < 8; op++) {
            float2 bb = __ldg(&b2[op]);
            u64 bv = pk2(bb.x, bb.y);
            acc[0][op] = bv;
            acc[1][op] = bv;
        }
    }
    const ulonglong2* wb = reinterpret_cast<const ulonglong2*>(W + (size_t)g * NF * NO);
    const int4* ip = reinterpret_cast<const int4*>(idx + g * NF);

    #pragma unroll
    for (int i6 = 0; i6 < 6; i6++) {
        int4 cv = __ldg(&ip[i6]);
        int cols[4] = {cv.x, cv.y, cv.z, cv.w};
        #pragma unroll
        for (int k = 0; k < 4; k++) {
            int f = i6 * 4 + k;
            int c = cols[k];
            float2 a = __half22float2(*ppc(sh, c, p));
            u64 d0 = pk2(a.x, a.x);
            u64 d1 = pk2(a.y, a.y);
            // o-half 0 (outputs 0..7)
            {
                ulonglong2 u0 = __ldg(&wb[f * 4 + 0]);
                ulonglong2 u1 = __ldg(&wb[f * 4 + 1]);
                acc[0][0] = fma2(d0, u0.x, acc[0][0]);
                acc[1][0] = fma2(d1, u0.x, acc[1][0]);
                acc[0][1] = fma2(d0, u0.y, acc[0][1]);
                acc[1][1] = fma2(d1, u0.y, acc[1][1]);
                acc[0][2] = fma2(d0, u1.x, acc[0][2]);
                acc[1][2] = fma2(d1, u1.x, acc[1][2]);
                acc[0][3] = fma2(d0, u1.y, acc[0][3]);
                acc[1][3] = fma2(d1, u1.y, acc[1][3]);
            }
            // o-half 1 (outputs 8..15)
            {
                ulonglong2 u2 = __ldg(&wb[f * 4 + 2]);
                ulonglong2 u3 = __ldg(&wb[f * 4 + 3]);
                acc[0][4] = fma2(d0, u2.x, acc[0][4]);
                acc[1][4] = fma2(d1, u2.x, acc[1][4]);
                acc[0][5] = fma2(d0, u2.y, acc[0][5]);
                acc[1][5] = fma2(d1, u2.y, acc[1][5]);
                acc[0][6] = fma2(d0, u3.x, acc[0][6]);
                acc[1][6] = fma2(d1, u3.x, acc[1][6]);
                acc[0][7] = fma2(d0, u3.y, acc[0][7]);
                acc[1][7] = fma2(d1, u3.y, acc[1][7]);
            }
        }
    }

    // tanh + fp16 writeback: 16 cols x 2 rows
    float v[2][NO];
    #pragma unroll
    for (int r = 0; r < 2; r++)
        #pragma unroll
        for (int op = 0; op < 8; op++)
            up2(acc[r][op], v[r][2 * op], v[r][2 * op + 1]);
    #pragma unroll
    for (int r = 0; r < 2; r++)
        #pragma unroll
        for (int o = 0; o < NO; o++)
            v[r][o] = tanhhw(v[r][o]);
    #pragma unroll
    for (int o = 0; o < NO; o++) {
        int c = colbase + g * NO + o;
        *pp(sh, c, p) = __floats2half2_rn(v[0][o], v[1][o]);
    }
}

__global__ void __launch_bounds__(NTHR, 1)
model_kernel(const float* __restrict__ x,
             const float* __restrict__ W1, const float* __restrict__ b1,
             const float* __restrict__ W2, const float* __restrict__ b2,
             const float* __restrict__ W3, const float* __restrict__ b3,
             const float* __restrict__ Wo, const float* __restrict__ bo,
             const int* __restrict__ idx1, const int* __restrict__ idx2,
             const int* __restrict__ idx3, const int* __restrict__ idxo,
             float* __restrict__ out)
{
    extern __shared__ __half sh[];  // [ACCC][32 rows] fp16, pair-hash swizzle
    const int t = threadIdx.x;
    const int rowbase = blockIdx.x * RT;

    // ---- Stage x tile (32 rows x 512 cols) fp32->fp16 into SMEM ----
    // thread = (row-half h, col c); LDG.32 coalesced over lanes, STS.32
    // bank-spread by HASH15's low col bits.
    {
        const int c = t & 511;
        const int h = t >> 9;            // 0 or 1: rows 16h..16h+15
        const float* xb = x + (size_t)rowbase * INC + c;
        #pragma unroll
        for (int it = 0; it < 8; it++) {
            int pr = h * 8 + it;         // row pair 0..15
            float v0 = __ldg(&xb[(2 * pr + 0) * INC]);
            float v1 = __ldg(&xb[(2 * pr + 1) * INC]);
            *pp(sh, c, pr) = __floats2half2_rn(v0, v1);
        }
    }
    __syncthreads();

    const int g = t >> 4;   // group 0..63
    const int p = t & 15;   // row pair 0..15

    glayer(sh, g, p, W1, b1, idx1, 512);
    __syncthreads();
    glayer(sh, g, p, W2, b2, idx2, 1536);
    __syncthreads();
    glayer(sh, g, p, W3, b3, idx3, 2560);
    __syncthreads();

    // ---- Output layer: 4 groups x 48 f x 16 o, linear, fp32 out ----
    {
        int ot = t & 15;
        int og = (t >> 4) & 3;
        int rp = t >> 6;                    // row pair 0..15
        float bias = __ldg(&bo[og * 16 + ot]);
        float h0 = bias, h1 = bias;
        const int* gi = idxo + og * 48;
        const float* w = Wo + og * 48 * 16 + ot;
        #pragma unroll
        for (int f = 0; f < 48; f++) {
            int c = __ldg(&gi[f]);
            float2 a = __half22float2(*ppc(sh, c, rp));
            float wf = __ldg(&w[f * 16]);
            h0 = fmaf(a.x, wf, h0);
            h1 = fmaf(a.y, wf, h1);
        }
        float* ob = out + (size_t)(rowbase + 2 * rp) * 64 + og * 16 + ot;
        ob[0]  = h0;
        ob[64] = h1;
    }
}

extern "C" void kernel_launch(void* const* d_in, const int* in_sizes, int n_in,
                              void* d_out, int out_size)
{
    const float* x   = (const float*)d_in[0];
    const float* W1  = (const float*)d_in[1];
    const float* b1  = (const float*)d_in[2];
    const float* W2  = (const float*)d_in[3];
    const float* b2  = (const float*)d_in[4];
    const float* W3  = (const float*)d_in[5];
    const float* b3  = (const float*)d_in[6];
    const float* Wo  = (const float*)d_in[7];
    const float* bo  = (const float*)d_in[8];
    const int*   i1  = (const int*)d_in[9];
    const int*   i2  = (const int*)d_in[10];
    const int*   i3  = (const int*)d_in[11];
    const int*   io  = (const int*)d_in[12];
    float*       out = (float*)d_out;

    cudaFuncSetAttribute(model_kernel,
                         cudaFuncAttributeMaxDynamicSharedMemorySize, SMEM_BYTES);
    model_kernel<<<NROWS / RT, NTHR, SMEM_BYTES>>>(
        x, W1, b1, W2, b2, W3, b3, Wo, bo, i1, i2, i3, io, out);
}

// round 9
// speedup vs baseline: 1.4864x; 1.4864x over previous
#include <cuda_runtime.h>
#include <cuda_fp16.h>

#define NROWS   16384
#define INC     512
#define NG      64
#define NF      24
#define NO      16
#define ACCC    3584
#define RT      32
#define NTHR    512
#define SMEM_BYTES (ACCC * RT * 2)   // 229376 bytes (fp16)

typedef unsigned long long u64;

static __device__ __forceinline__ u64 pk2(float a, float b) {
    u64 r;
    asm("mov.b64 %0, {%1, %2};" : "=l"(r) : "f"(a), "f"(b));
    return r;
}
static __device__ __forceinline__ void up2(u64 v, float &a, float &b) {
    asm("mov.b64 {%0, %1}, %2;" : "=f"(a), "=f"(b) : "l"(v));
}
static __device__ __forceinline__ u64 fma2(u64 a, u64 b, u64 c) {
    u64 d;
    asm("fma.rn.f32x2 %0, %1, %2, %3;" : "=l"(d) : "l"(a), "l"(b), "l"(c));
    return d;
}
static __device__ __forceinline__ float tanhhw(float x) {
    float y;
    asm("tanh.approx.f32 %0, %1;" : "=f"(y) : "f"(x));
    return y;
}

// fp16 tile [col][32 rows]; element (c, r) lives in 8B chunk j=r/4,
// physical chunk slot = j ^ CHASH(c): spreads banks for random gathers,
// the staging stores, and the sequential-column writeback.
#define CHASH(c)   ((((c) ^ ((c) >> 3)) & 7))

static __device__ __forceinline__ const __half* colptr(const __half* sh, int c, int j) {
    return sh + c * RT + ((j ^ CHASH(c)) << 2);
}
static __device__ __forceinline__ __half* colptrw(__half* sh, int c, int j) {
    return sh + c * RT + ((j ^ CHASH(c)) << 2);
}
static __device__ __forceinline__ void store4(__half* sh, int c, int j,
                                              float v0, float v1, float v2, float v3) {
    __half2 ha = __floats2half2_rn(v0, v1);
    __half2 hb = __floats2half2_rn(v2, v3);
    uint2 st;
    st.x = reinterpret_cast<unsigned&>(ha);
    st.y = reinterpret_cast<unsigned&>(hb);
    *reinterpret_cast<uint2*>(colptrw(sh, c, j)) = st;
}

// Thread = (g, q): group g, row-quad q (rows 4q..4q+3), all 16 outputs.
// Two o-half passes (outputs 8h..8h+7) with rolling weight/activation
// prefetch; acc[r][j] = f32x2 over outputs (8h+2j, 8h+2j+1) for local row r.
static __device__ __forceinline__ void glayer(__half* sh, int g, int q,
                                              const float* __restrict__ W,
                                              const float* __restrict__ bia,
                                              const int* __restrict__ idx,
                                              int colbase)
{
    int cols[NF];
    const int4* ip = reinterpret_cast<const int4*>(idx + g * NF);
    #pragma unroll
    for (int i = 0; i < NF / 4; i++) {
        int4 v = __ldg(&ip[i]);
        cols[4 * i + 0] = v.x; cols[4 * i + 1] = v.y;
        cols[4 * i + 2] = v.z; cols[4 * i + 3] = v.w;
    }
    const ulonglong2* wb = reinterpret_cast<const ulonglong2*>(W + (size_t)g * NF * NO);
    const float2*     b2 = reinterpret_cast<const float2*>(bia + g * NO);

    #pragma unroll
    for (int h = 0; h < 2; h++) {
        u64 acc[4][4];
        #pragma unroll
        for (int j = 0; j < 4; j++) {
            float2 bb = __ldg(&b2[4 * h + j]);
            u64 bv = pk2(bb.x, bb.y);
            acc[0][j] = bv; acc[1][j] = bv; acc[2][j] = bv; acc[3][j] = bv;
        }

        // rolling prefetch buffers (f = 0 primed)
        ulonglong2 wa = __ldg(&wb[2 * h]);
        ulonglong2 wc = __ldg(&wb[2 * h + 1]);
        uint2 ar = *reinterpret_cast<const uint2*>(colptr(sh, cols[0], q));

        #pragma unroll
        for (int f = 0; f < NF; f++) {
            ulonglong2 na, nc;
            uint2 nr;
            if (f < NF - 1) {
                na = __ldg(&wb[(f + 1) * 4 + 2 * h]);
                nc = __ldg(&wb[(f + 1) * 4 + 2 * h + 1]);
                nr = *reinterpret_cast<const uint2*>(colptr(sh, cols[f + 1], q));
            }
            float2 f01 = __half22float2(reinterpret_cast<__half2&>(ar.x));
            float2 f23 = __half22float2(reinterpret_cast<__half2&>(ar.y));
            u64 d0 = pk2(f01.x, f01.x);
            u64 d1 = pk2(f01.y, f01.y);
            u64 d2 = pk2(f23.x, f23.x);
            u64 d3 = pk2(f23.y, f23.y);
            u64 u[4] = {wa.x, wa.y, wc.x, wc.y};
            #pragma unroll
            for (int j = 0; j < 4; j++) {
                acc[0][j] = fma2(d0, u[j], acc[0][j]);
                acc[1][j] = fma2(d1, u[j], acc[1][j]);
                acc[2][j] = fma2(d2, u[j], acc[2][j]);
                acc[3][j] = fma2(d3, u[j], acc[3][j]);
            }
            if (f < NF - 1) { wa = na; wc = nc; ar = nr; }
        }

        // tanh + fp16 writeback for this o-half: 8 cols x 4 rows
        float v[4][8];
        #pragma unroll
        for (int r = 0; r < 4; r++)
            #pragma unroll
            for (int j = 0; j < 4; j++)
                up2(acc[r][j], v[r][2 * j], v[r][2 * j + 1]);
        #pragma unroll
        for (int r = 0; r < 4; r++)
            #pragma unroll
            for (int o = 0; o < 8; o++)
                v[r][o] = tanhhw(v[r][o]);
        #pragma unroll
        for (int o = 0; o < 8; o++) {
            int c = colbase + g * NO + 8 * h + o;
            store4(sh, c, q, v[0][o], v[1][o], v[2][o], v[3][o]);
        }
    }
}

__global__ void __launch_bounds__(NTHR, 1)
model_kernel(const float* __restrict__ x,
             const float* __restrict__ W1, const float* __restrict__ b1,
             const float* __restrict__ W2, const float* __restrict__ b2,
             const float* __restrict__ W3, const float* __restrict__ b3,
             const float* __restrict__ Wo, const float* __restrict__ bo,
             const int* __restrict__ idx1, const int* __restrict__ idx2,
             const int* __restrict__ idx3, const int* __restrict__ idxo,
             float* __restrict__ out)
{
    extern __shared__ __half sh[];  // [ACCC][32 rows] fp16, chunk-hash swizzle
    const int t = threadIdx.x;
    const int rowbase = blockIdx.x * RT;

    // ---- Stage x tile (32 rows x 512 cols) fp32->fp16 into SMEM ----
    // thread = column; LDG.32 coalesced across lanes, stores hash-spread.
    {
        const float* xb = x + (size_t)rowbase * INC;
        const int c = t;
        #pragma unroll
        for (int it = 0; it < 8; it++) {
            float v0 = __ldg(&xb[(4 * it + 0) * INC + c]);
            float v1 = __ldg(&xb[(4 * it + 1) * INC + c]);
            float v2 = __ldg(&xb[(4 * it + 2) * INC + c]);
            float v3 = __ldg(&xb[(4 * it + 3) * INC + c]);
            store4(sh, c, it, v0, v1, v2, v3);
        }
    }
    __syncthreads();

    const int g = t >> 3;   // group 0..63
    const int q = t & 7;    // row-quad 0..7

    glayer(sh, g, q, W1, b1, idx1, 512);
    __syncthreads();
    glayer(sh, g, q, W2, b2, idx2, 1536);
    __syncthreads();
    glayer(sh, g, q, W3, b3, idx3, 2560);
    __syncthreads();

    // ---- Output layer: 4 groups x 48 f x 16 o, linear, fp32 out ----
    {
        int ot = t & 15;
        int og = (t >> 4) & 3;
        int rq = t >> 6;                    // row-quad 0..7
        float bias = __ldg(&bo[og * 16 + ot]);
        float h0 = bias, h1 = bias, h2 = bias, h3 = bias;
        const int* gi = idxo + og * 48;
        const float* w = Wo + og * 48 * 16 + ot;
        #pragma unroll
        for (int f = 0; f < 48; f++) {
            int c = __ldg(&gi[f]);
            uint2 raw = *reinterpret_cast<const uint2*>(colptr(sh, c, rq));
            float2 f01 = __half22float2(reinterpret_cast<__half2&>(raw.x));
            float2 f23 = __half22float2(reinterpret_cast<__half2&>(raw.y));
            float wf = __ldg(&w[f * 16]);
            h0 = fmaf(f01.x, wf, h0);
            h1 = fmaf(f01.y, wf, h1);
            h2 = fmaf(f23.x, wf, h2);
            h3 = fmaf(f23.y, wf, h3);
        }
        float* ob = out + (size_t)(rowbase + rq * 4) * 64 + og * 16 + ot;
        ob[0]   = h0;
        ob[64]  = h1;
        ob[128] = h2;
        ob[192] = h3;
    }
}

extern "C" void kernel_launch(void* const* d_in, const int* in_sizes, int n_in,
                              void* d_out, int out_size)
{
    const float* x   = (const float*)d_in[0];
    const float* W1  = (const float*)d_in[1];
    const float* b1  = (const float*)d_in[2];
    const float* W2  = (const float*)d_in[3];
    const float* b2  = (const float*)d_in[4];
    const float* W3  = (const float*)d_in[5];
    const float* b3  = (const float*)d_in[6];
    const float* Wo  = (const float*)d_in[7];
    const float* bo  = (const float*)d_in[8];
    const int*   i1  = (const int*)d_in[9];
    const int*   i2  = (const int*)d_in[10];
    const int*   i3  = (const int*)d_in[11];
    const int*   io  = (const int*)d_in[12];
    float*       out = (float*)d_out;

    cudaFuncSetAttribute(model_kernel,
                         cudaFuncAttributeMaxDynamicSharedMemorySize, SMEM_BYTES);
    model_kernel<<<NROWS / RT, NTHR, SMEM_BYTES>>>(
        x, W1, b1, W2, b2, W3, b3, Wo, bo, i1, i2, i3, io, out);
}